// round 8
// baseline (speedup 1.0000x reference)
#include <cuda_runtime.h>
#include <cstdint>

// LocallyConnected2d: B=16, C=32, H=W=64, K=3, pad=1, stride=1
// out[b, o, l] = sum_i patch[b, l, i] * w[l, i, o] + bias[l, o]
//
// CTA = 64 thr = 2 warps = 2x2 locations. Warp wid=dy covers 2 locations
// (dx = lane>>4). Lane owns 4 output channels (oc0 = 4*(lane&15)), all 16
// batches, packed f32x2 (acc[4][8]).
// Weights: per-thread cp.async.cg 16B chunks into a 2-stage smem ring
// (commit_group/wait_group + __syncthreads). Unbounded MLP, no dest regs.
// Patch: 8-channel tile (8KB), restaged 4x, coalesced loads (col-fastest).

#define BATCH   16
#define CIN     32
#define OC      64
#define TILE_C  8
#define TILE_ELEMS (TILE_C * 4 * 4 * BATCH)   // 2048 floats = 8KB
#define WLOC_F   580                           // 576 floats + 16B pad
#define WSTAGE_F (4 * WLOC_F)                  // 2320 floats per stage

struct __align__(128) Smem {
    float tile[TILE_ELEMS];          // [cc(8)][r(4)][col(4)][b(16)]  8192B
    float wbuf[2][WSTAGE_F];         // [stage][loc*580 + k*64 + oc]  18560B
};

__device__ __forceinline__ void cp16(uint32_t dst, const float* src) {
    asm volatile("cp.async.cg.shared.global [%0], [%1], 16;"
                 :: "r"(dst), "l"(src) : "memory");
}
__device__ __forceinline__ void cp_commit() {
    asm volatile("cp.async.commit_group;" ::: "memory");
}
__device__ __forceinline__ void cp_wait1() {
    asm volatile("cp.async.wait_group 1;" ::: "memory");
}

__global__ __launch_bounds__(64, 8) void lc2d_kernel(
    const float* __restrict__ x,      // (16, 32, 64, 64)
    const float* __restrict__ w,      // (4096, 288, 64)
    const float* __restrict__ bias,   // (4096, 64)
    float* __restrict__ out)          // (16, 64, 64, 64)
{
    __shared__ Smem sm;

    const int cta = blockIdx.x;            // 1024 CTAs = 32x32 tiles of 2x2
    const int th  = cta >> 5;
    const int tw  = cta & 31;
    const int H0  = 2 * th - 1;
    const int W0  = 2 * tw - 1;
    const int tid = threadIdx.x;

    const int wid    = tid >> 5;
    const int lane   = tid & 31;
    const int dy     = wid;
    const int dx     = lane >> 4;
    const int lane16 = lane & 15;
    const int oc0    = 4 * lane16;
    const int locIdx = dy * 2 + dx;
    const int l0     = ((2 * th) << 6) + 2 * tw;
    const int l      = l0 + (dy << 6) + dx;

    const uint32_t smb    = (uint32_t)__cvta_generic_to_shared(&sm);
    const uint32_t tile_u = smb;                                  // offset 0
    const uint32_t wbuf_u = smb + sizeof(float) * TILE_ELEMS;     // 8192

    // Per-location global row base (floats): w + ll*18432 + c*576
    int llsrc[4];
#pragma unroll
    for (int li = 0; li < 4; li++)
        llsrc[li] = (l0 + ((li >> 1) << 6) + (li & 1)) * 18432;

    // ---- Weight producer: issue channel c into stage s ----
    // 576 16B-chunks per channel (4 loc x 144); thread does 9 (tid, tid+64, ...)
    auto issue_weights = [&](int c, int s) {
#pragma unroll
        for (int j = 0; j < 9; j++) {
            int e   = tid + 64 * j;          // 0..575
            int li  = e / 144;
            int i   = e - li * 144;
            const float* src = w + llsrc[li] + c * 576 + i * 4;
            uint32_t dst = wbuf_u + (uint32_t)((s * WSTAGE_F + li * WLOC_F + i * 4) * 4);
            cp16(dst, src);
        }
    };

    // ---- Prologue: channels 0 and 1 in flight immediately ----
    issue_weights(0, 0); cp_commit();
    issue_weights(1, 1); cp_commit();

    // acc[o][j] : oc=oc0+o, batches (2j, 2j+1) packed f32x2
    unsigned long long acc[4][8];
#pragma unroll
    for (int o = 0; o < 4; o++)
#pragma unroll
        for (int j = 0; j < 8; j++) acc[o][j] = 0ull;

    const uint32_t pconst = tile_u + (uint32_t)(dy * 256 + dx * 64);
    const uint32_t wconst = wbuf_u + (uint32_t)((locIdx * WLOC_F + oc0) * 4);

    for (int c = 0; c < CIN; c++) {
        const int s  = c & 1;
        const int cc = c & 7;

        // ---- Restage patch tile every 8 channels (coalesced: col fastest) ----
        if (cc == 0) {
            if (c) __syncthreads();          // prior tile reads done (post-compute
                                             // sync of c-1 also precedes this)
#pragma unroll 4
            for (int e = tid; e < TILE_ELEMS; e += 64) {
                int col = e & 3;
                int b   = (e >> 2) & 15;
                int r   = (e >> 6) & 3;
                int ccc = e >> 8;
                int ch  = c + ccc;
                int h   = H0 + r;
                int ww  = W0 + col;
                float v = 0.0f;
                if ((unsigned)h < 64u && (unsigned)ww < 64u)
                    v = x[((((b * CIN + ch) << 6) + h) << 6) + ww];
                sm.tile[((ccc * 4 + r) * 4 + col) * BATCH + b] = v;
            }
        }

        cp_wait1();          // this thread's copies for channel c complete
        __syncthreads();     // weights + tile visible CTA-wide

        const uint32_t pbase = pconst + (uint32_t)(cc * 1024);
        const uint32_t wb    = wconst + (uint32_t)(s * WSTAGE_F * 4);

#pragma unroll
        for (int k = 0; k < 9; k++) {
            const int ki = k / 3;
            const int kj = k - ki * 3;

            float4 wv;
            asm("ld.shared.v4.f32 {%0,%1,%2,%3}, [%4];"
                : "=f"(wv.x), "=f"(wv.y), "=f"(wv.z), "=f"(wv.w)
                : "r"(wb + (uint32_t)(k * 256)));

            unsigned long long w2[4];
            asm("mov.b64 %0, {%1, %1};" : "=l"(w2[0]) : "f"(wv.x));
            asm("mov.b64 %0, {%1, %1};" : "=l"(w2[1]) : "f"(wv.y));
            asm("mov.b64 %0, {%1, %1};" : "=l"(w2[2]) : "f"(wv.z));
            asm("mov.b64 %0, {%1, %1};" : "=l"(w2[3]) : "f"(wv.w));

            uint32_t a = pbase + (uint32_t)(ki * 256 + kj * 64);
            unsigned long long p0, p1, p2, p3, p4, p5, p6, p7;
            asm("ld.shared.v2.b64 {%0,%1}, [%2];" : "=l"(p0), "=l"(p1) : "r"(a));
            asm("ld.shared.v2.b64 {%0,%1}, [%2];" : "=l"(p2), "=l"(p3) : "r"(a + 16));
            asm("ld.shared.v2.b64 {%0,%1}, [%2];" : "=l"(p4), "=l"(p5) : "r"(a + 32));
            asm("ld.shared.v2.b64 {%0,%1}, [%2];" : "=l"(p6), "=l"(p7) : "r"(a + 48));

#pragma unroll
            for (int o = 0; o < 4; o++) {
                asm("fma.rn.f32x2 %0, %1, %2, %0;" : "+l"(acc[o][0]) : "l"(p0), "l"(w2[o]));
                asm("fma.rn.f32x2 %0, %1, %2, %0;" : "+l"(acc[o][1]) : "l"(p1), "l"(w2[o]));
                asm("fma.rn.f32x2 %0, %1, %2, %0;" : "+l"(acc[o][2]) : "l"(p2), "l"(w2[o]));
                asm("fma.rn.f32x2 %0, %1, %2, %0;" : "+l"(acc[o][3]) : "l"(p3), "l"(w2[o]));
                asm("fma.rn.f32x2 %0, %1, %2, %0;" : "+l"(acc[o][4]) : "l"(p4), "l"(w2[o]));
                asm("fma.rn.f32x2 %0, %1, %2, %0;" : "+l"(acc[o][5]) : "l"(p5), "l"(w2[o]));
                asm("fma.rn.f32x2 %0, %1, %2, %0;" : "+l"(acc[o][6]) : "l"(p6), "l"(w2[o]));
                asm("fma.rn.f32x2 %0, %1, %2, %0;" : "+l"(acc[o][7]) : "l"(p7), "l"(w2[o]));
            }
        }

        __syncthreads();     // ALL threads done reading wbuf[s] before overwrite

        if (c + 2 < CIN)
            issue_weights(c + 2, s);
        cp_commit();         // uniform: empty group when nothing issued
    }

    // ---- Epilogue: bias + scatter stores ----
    float4 bv = *(const float4*)(bias + l * OC + oc0);
    const float bvs[4] = {bv.x, bv.y, bv.z, bv.w};
    float* op = out + (size_t)oc0 * 4096 + l;

#pragma unroll
    for (int o = 0; o < 4; o++) {
        float* opo = op + (size_t)o * 4096;
#pragma unroll
        for (int j = 0; j < 8; j++) {
            float lo, hi;
            asm("mov.b64 {%0, %1}, %2;" : "=f"(lo), "=f"(hi) : "l"(acc[o][j]));
            opo[(size_t)(2 * j) * (OC * 4096)]     = lo + bvs[o];
            opo[(size_t)(2 * j + 1) * (OC * 4096)] = hi + bvs[o];
        }
    }
}

extern "C" void kernel_launch(void* const* d_in, const int* in_sizes, int n_in,
                              void* d_out, int out_size) {
    const float* x    = (const float*)d_in[0];
    const float* wgt  = (const float*)d_in[1];
    const float* bias = (const float*)d_in[2];
    float* out        = (float*)d_out;

    lc2d_kernel<<<1024, 64>>>(x, wgt, bias, out);
}

// round 9
// speedup vs baseline: 1.0220x; 1.0220x over previous
#include <cuda_runtime.h>
#include <cstdint>

// LocallyConnected2d: B=16, C=32, H=W=64, K=3, pad=1, stride=1
// out[b, o, l] = sum_i patch[b, l, i] * w[l, i, o] + bias[l, o]
//
// CTA = 64 thr = 2 warps = 2x2 locations. Warp wid = dy row, covers 2
// locations (dx = lane bit). lane = bhalf(1) | dx(1) | ocg(3):
//   owns oc = 8*ocg..+7, batches 8*bhalf..+7 of location (dy,dx).
// Weights: WARP-AUTONOMOUS cp.async 2-stage ring (4608B/channel/warp),
// synced with wait_group+__syncwarp only -> no CTA barriers per channel.
// Patch: 8-channel tile (8KB), restaged 4x (the only CTA syncs).

#define BATCH   16
#define CIN     32
#define OC      64
#define TILE_C  8
#define TILE_ELEMS (TILE_C * 4 * 4 * BATCH)   // 2048 floats = 8KB
#define WLOC_B   2320                          // 2304B + 16B pad
#define WSTAGE_B (2 * WLOC_B)                  // 4640B per stage (2 loc)
#define WWARP_B  (2 * WSTAGE_B)                // 9280B per warp (2 stages)

struct __align__(128) Smem {
    float tile[TILE_ELEMS];              // [cc(8)][r(4)][col(4)][b(16)]
    char  wbuf[2][WWARP_B];              // [warp][stage][loc][k][64oc]
};

__device__ __forceinline__ void cp16(uint32_t dst, const float* src) {
    asm volatile("cp.async.cg.shared.global [%0], [%1], 16;"
                 :: "r"(dst), "l"(src) : "memory");
}
__device__ __forceinline__ void cp_commit() {
    asm volatile("cp.async.commit_group;" ::: "memory");
}
__device__ __forceinline__ void cp_wait1() {
    asm volatile("cp.async.wait_group 1;" ::: "memory");
}

__global__ __launch_bounds__(64, 8) void lc2d_kernel(
    const float* __restrict__ x,      // (16, 32, 64, 64)
    const float* __restrict__ w,      // (4096, 288, 64)
    const float* __restrict__ bias,   // (4096, 64)
    float* __restrict__ out)          // (16, 64, 64, 64)
{
    __shared__ Smem sm;

    const int cta = blockIdx.x;            // 1024 CTAs = 32x32 tiles of 2x2
    const int th  = cta >> 5;
    const int tw  = cta & 31;
    const int H0  = 2 * th - 1;
    const int W0  = 2 * tw - 1;
    const int tid = threadIdx.x;

    const int wid   = tid >> 5;        // = dy
    const int lane  = tid & 31;
    const int dy    = wid;
    const int bhalf = lane >> 4;
    const int dx    = (lane >> 3) & 1;
    const int ocg   = lane & 7;
    const int oc0   = ocg * 8;
    const int l0    = ((2 * th) << 6) + 2 * tw;
    const int l     = l0 + (dy << 6) + dx;

    const uint32_t smb    = (uint32_t)__cvta_generic_to_shared(&sm);
    const uint32_t tile_u = smb;
    const uint32_t wwarp  = smb + sizeof(float) * TILE_ELEMS + (uint32_t)(wid * WWARP_B);

    // Warp's two source locations (dx = 0, 1)
    const size_t src0 = (size_t)(l0 + (dy << 6)) * 18432;       // floats
    const size_t src1 = src0 + 18432;

    // ---- Warp-autonomous weight producer: channel c -> stage s ----
    // 288 16B-chunks per channel (2 loc x 144); lane does 9 (lane, lane+32, ...)
    auto issue_weights = [&](int c, int s) {
#pragma unroll
        for (int j = 0; j < 9; j++) {
            int e  = lane + 32 * j;          // 0..287
            int li = e / 144;
            int i  = e - li * 144;
            const float* src = w + (li ? src1 : src0) + c * 576 + i * 4;
            uint32_t dst = wwarp + (uint32_t)(s * WSTAGE_B + li * WLOC_B + i * 16);
            cp16(dst, src);
        }
        cp_commit();
    };

    // ---- Prologue: channels 0,1 in flight ----
    issue_weights(0, 0);
    issue_weights(1, 1);

    // acc[o][j] : oc = oc0+o, batches (bhalf*8 + 2j, +1) packed f32x2
    unsigned long long acc[8][4];
#pragma unroll
    for (int o = 0; o < 8; o++)
#pragma unroll
        for (int j = 0; j < 4; j++) acc[o][j] = 0ull;

    const uint32_t pconst = tile_u + (uint32_t)(dy * 1024 + dx * 256 + bhalf * 32) - 0
                          + 0;   // note: dy/dx select within r/col dims below
    // Patch addr for (cc,ki,kj): tile[cc][dy+ki][dx+kj][b]; [cc]=1024B, [r]=256B, [col]=64B
    const uint32_t pbase0 = tile_u + (uint32_t)(dy * 256 + dx * 64 + bhalf * 32);
    const uint32_t wconst = wwarp + (uint32_t)(dx * WLOC_B + ocg * 32);

    for (int c = 0; c < CIN; c++) {
        const int s  = c & 1;
        const int cc = c & 7;

        // ---- Restage patch tile every 8 channels (only CTA syncs) ----
        if (cc == 0) {
            __syncthreads();                 // all reads of old tile done
#pragma unroll 4
            for (int e = tid; e < TILE_ELEMS; e += 64) {
                int col = e & 3;
                int b   = (e >> 2) & 15;
                int r   = (e >> 6) & 3;
                int ccc = e >> 8;
                int ch  = c + ccc;
                int h   = H0 + r;
                int ww  = W0 + col;
                float v = 0.0f;
                if ((unsigned)h < 64u && (unsigned)ww < 64u)
                    v = x[((((b * CIN + ch) << 6) + h) << 6) + ww];
                sm.tile[((ccc * 4 + r) * 4 + col) * BATCH + b] = v;
            }
            __syncthreads();                 // new tile visible
        }

        cp_wait1();          // this lane's copies for channel c done
        __syncwarp();        // stage visible warp-wide

        const uint32_t pbase = pbase0 + (uint32_t)(cc * 1024);
        const uint32_t wb    = wconst + (uint32_t)(s * WSTAGE_B);

#pragma unroll
        for (int k = 0; k < 9; k++) {
            const int ki = k / 3;
            const int kj = k - ki * 3;

            float w8[8];
            asm("ld.shared.v4.f32 {%0,%1,%2,%3}, [%4];"
                : "=f"(w8[0]), "=f"(w8[1]), "=f"(w8[2]), "=f"(w8[3])
                : "r"(wb + (uint32_t)(k * 256)));
            asm("ld.shared.v4.f32 {%0,%1,%2,%3}, [%4];"
                : "=f"(w8[4]), "=f"(w8[5]), "=f"(w8[6]), "=f"(w8[7])
                : "r"(wb + (uint32_t)(k * 256 + 16)));

            uint32_t a = pbase + (uint32_t)(ki * 256 + kj * 64);
            unsigned long long p0, p1, p2, p3;
            asm("ld.shared.v2.b64 {%0,%1}, [%2];" : "=l"(p0), "=l"(p1) : "r"(a));
            asm("ld.shared.v2.b64 {%0,%1}, [%2];" : "=l"(p2), "=l"(p3) : "r"(a + 16));

#pragma unroll
            for (int o = 0; o < 8; o++) {
                unsigned long long w2;
                asm("mov.b64 %0, {%1, %1};" : "=l"(w2) : "f"(w8[o]));
                asm("fma.rn.f32x2 %0, %1, %2, %0;" : "+l"(acc[o][0]) : "l"(p0), "l"(w2));
                asm("fma.rn.f32x2 %0, %1, %2, %0;" : "+l"(acc[o][1]) : "l"(p1), "l"(w2));
                asm("fma.rn.f32x2 %0, %1, %2, %0;" : "+l"(acc[o][2]) : "l"(p2), "l"(w2));
                asm("fma.rn.f32x2 %0, %1, %2, %0;" : "+l"(acc[o][3]) : "l"(p3), "l"(w2));
            }
        }

        // Refill freed stage with channel c+2 (only this warp reads/writes it)
        if (c + 2 < CIN)
            issue_weights(c + 2, s);
        else
            cp_commit();     // keep group count uniform
    }

    // ---- Epilogue: bias + scatter stores ----
    float bb[8];
    {
        float4 b0 = *(const float4*)(bias + l * OC + oc0);
        float4 b1 = *(const float4*)(bias + l * OC + oc0 + 4);
        bb[0]=b0.x; bb[1]=b0.y; bb[2]=b0.z; bb[3]=b0.w;
        bb[4]=b1.x; bb[5]=b1.y; bb[6]=b1.z; bb[7]=b1.w;
    }
    float* op = out + (size_t)oc0 * 4096 + l + ((size_t)(bhalf * 8) << 18);

#pragma unroll
    for (int o = 0; o < 8; o++) {
        float* opo = op + (size_t)o * 4096;
#pragma unroll
        for (int j = 0; j < 4; j++) {
            float lo, hi;
            asm("mov.b64 {%0, %1}, %2;" : "=f"(lo), "=f"(hi) : "l"(acc[o][j]));
            opo[((size_t)(2 * j) << 18)]     = lo + bb[o];
            opo[((size_t)(2 * j + 1) << 18)] = hi + bb[o];
        }
    }
}

extern "C" void kernel_launch(void* const* d_in, const int* in_sizes, int n_in,
                              void* d_out, int out_size) {
    const float* x    = (const float*)d_in[0];
    const float* wgt  = (const float*)d_in[1];
    const float* bias = (const float*)d_in[2];
    float* out        = (float*)d_out;

    lc2d_kernel<<<1024, 64>>>(x, wgt, bias, out);
}